// round 3
// baseline (speedup 1.0000x reference)
#include <cuda_runtime.h>
#include <cuda_fp16.h>
#include <cstdint>

#define HSZ    256
#define BATCH  512
#define TSTEPS 1024
#define G4     1024
#define FIN    10
#define PA     264   // smem pitch in halves
#define NB     128   // persistent CTAs (all co-resident)

// ---------------- device scratch ----------------
__device__ __half g_whh0[G4 * HSZ];
__device__ __half g_wih1[G4 * HSZ];
__device__ __half g_whh1[G4 * HSZ];
__device__ __half g_advw1[HSZ * HSZ];
__device__ float  g_bias0[G4];
__device__ float  g_bias1[G4];
__device__ float  g_xT[(size_t)TSTEPS * BATCH * FIN];
__device__ __half g_h1[2][BATCH * HSZ];
__device__ __half g_hs[(size_t)TSTEPS * BATCH * HSZ];   // h2 history == h2 state
__device__ float  g_scores[TSTEPS * BATCH];
__device__ unsigned g_bar_count;
__device__ unsigned g_bar_gen;

__device__ __forceinline__ float sigmoidf_(float x) { return 1.0f / (1.0f + expf(-x)); }

__device__ __forceinline__ float dot10(const float* a, const float* b) {
    float s = 0.f;
#pragma unroll
    for (int f = 0; f < FIN; f++) s += a[f] * b[f];
    return s;
}

// Stage [128 x 256] half tile (row stride 256) into smem pitch PA.
__device__ __forceinline__ void stageA(__half* At, const __half* __restrict__ src, int tid) {
    for (int i = tid; i < 128 * 32; i += 256) {
        int r = i >> 5, c = (i & 31) * 8;
        *(uint4*)(At + r * PA + c) = *(const uint4*)(src + r * HSZ + c);
    }
}

// 8 warps: warp w covers rows [w*16, w*16+16). NT gate-strips of 8 cols.
template <int NT>
__device__ __forceinline__ void warp_mma(const __half* At, const __half* Ws,
                                         int w, int lane, float (&acc)[NT][4], int K) {
    int g = lane >> 2, tq = lane & 3;
    const __half* Ab = At + (w * 16 + g) * PA + 2 * tq;
    const __half* Bb = Ws + g * PA + 2 * tq;
    for (int kc = 0; kc < K; kc += 16) {
        uint32_t a0 = *(const uint32_t*)(Ab + kc);
        uint32_t a1 = *(const uint32_t*)(Ab + kc + 8 * PA);
        uint32_t a2 = *(const uint32_t*)(Ab + kc + 8);
        uint32_t a3 = *(const uint32_t*)(Ab + kc + 8 * PA + 8);
#pragma unroll
        for (int nt = 0; nt < NT; nt++) {
            const __half* Bp = Bb + nt * 8 * PA + kc;
            uint32_t b0 = *(const uint32_t*)(Bp);
            uint32_t b1 = *(const uint32_t*)(Bp + 8);
            asm volatile(
                "mma.sync.aligned.m16n8k16.row.col.f32.f16.f16.f32 "
                "{%0,%1,%2,%3},{%4,%5,%6,%7},{%8,%9},{%0,%1,%2,%3};\n"
                : "+f"(acc[nt][0]), "+f"(acc[nt][1]), "+f"(acc[nt][2]), "+f"(acc[nt][3])
                : "r"(a0), "r"(a1), "r"(a2), "r"(a3), "r"(b0), "r"(b1));
        }
    }
}

// Sense-reversing grid barrier. Safe: all NB CTAs co-resident (1 CTA/SM).
__device__ __forceinline__ void grid_barrier() {
    __syncthreads();
    if (threadIdx.x == 0) {
        __threadfence();   // fence.gpu: publish our writes, flush L1
        unsigned gen = *(volatile unsigned*)&g_bar_gen;
        unsigned t = atomicAdd(&g_bar_count, 1u);
        if (t == NB - 1) {
            g_bar_count = 0;
            __threadfence();
            *(volatile unsigned*)&g_bar_gen = gen + 1;
        } else {
            while (*(volatile unsigned*)&g_bar_gen == gen) { __nanosleep(32); }
        }
        __threadfence();   // acquire: invalidate L1 before re-reading h1/h2
    }
    __syncthreads();
}

// ---------------- prologue ----------------
__global__ void k_prep(const float* __restrict__ whh0, const float* __restrict__ wih1,
                       const float* __restrict__ whh1, const float* __restrict__ advw1,
                       const float* __restrict__ bih0, const float* __restrict__ bhh0,
                       const float* __restrict__ bih1, const float* __restrict__ bhh1) {
    int i = blockIdx.x * blockDim.x + threadIdx.x;
    if (i == 0) { g_bar_count = 0; g_bar_gen = 0; }
    if (i < G4 * HSZ) {
        g_whh0[i] = __float2half(whh0[i]);
        g_wih1[i] = __float2half(wih1[i]);
        g_whh1[i] = __float2half(whh1[i]);
    }
    if (i < HSZ * HSZ) g_advw1[i] = __float2half(advw1[i]);
    if (i < G4) { g_bias0[i] = bih0[i] + bhh0[i]; g_bias1[i] = bih1[i] + bhh1[i]; }
}

__global__ void k_xpose(const float* __restrict__ x) {
    int idx = blockIdx.x * blockDim.x + threadIdx.x;   // idx = b*T + t
    if (idx < BATCH * TSTEPS) {
        int b = idx >> 10, t = idx & 1023;
        const float* src = x + (size_t)idx * FIN;
        float* dst = g_xT + ((size_t)t * BATCH + b) * FIN;
#pragma unroll
        for (int f = 0; f < FIN; f++) dst[f] = src[f];
    }
}

// ---------------- persistent LSTM kernel ----------------
__global__ void __launch_bounds__(256, 1) k_main(const float* __restrict__ wih0) {
    extern __shared__ char smraw[];
    __half* At  = (__half*)smraw;               // 128 x PA
    __half* Ws0 = At  + 128 * PA;               // whh0 slice (32 x PA)
    __half* Ws1 = Ws0 + 32 * PA;                // wih1 slice
    __half* Ws2 = Ws1 + 32 * PA;                // whh1 slice
    float*  xsm = (float*)(Ws2 + 32 * PA);      // 128 x 10
    float*  wxs = xsm + 128 * FIN;              // 32 x 10 (wih0 slice)
    float*  b0s = wxs + 32 * FIN;               // 32
    float*  b1s = b0s + 32;                     // 32

    int tid = threadIdx.x;
    int m0 = (blockIdx.x >> 5) * 128;           // batch tile
    int hbase = (blockIdx.x & 31) * 8;          // h-slice

    // one-time weight staging
    for (int i = tid; i < 32 * 32; i += 256) {
        int r = i >> 5, c = (i & 31) * 8;
        int s = r >> 3, n = r & 7;
        int grow = (s * 256 + hbase + n) * HSZ + c;
        *(uint4*)(Ws0 + r * PA + c) = *(const uint4*)(g_whh0 + grow);
        *(uint4*)(Ws1 + r * PA + c) = *(const uint4*)(g_wih1 + grow);
        *(uint4*)(Ws2 + r * PA + c) = *(const uint4*)(g_whh1 + grow);
    }
    for (int i = tid; i < 32 * FIN; i += 256) {
        int r = i / FIN, f = i - r * FIN;
        int s = r >> 3, n = r & 7;
        wxs[i] = wih0[(s * 256 + hbase + n) * FIN + f];
    }
    if (tid < 32) {
        int s = tid >> 3, n = tid & 7;
        b0s[tid] = g_bias0[s * 256 + hbase + n];
        b1s[tid] = g_bias1[s * 256 + hbase + n];
    }

    int w = tid >> 5, lane = tid & 31, g = lane >> 2, tq = lane & 3;
    // thread-owned coordinates (j = 0..3): row rl_j, col cl_j
    int rl0 = w * 16 + g;                       // rows for j=0,1; +8 for j=2,3
    int colb = hbase + 2 * tq;                  // base col (cl = 2tq + (j&1))

    float c1v[4] = {0.f, 0.f, 0.f, 0.f};
    float c2v[4] = {0.f, 0.f, 0.f, 0.f};

    // stage x(0)
    for (int i = tid; i < 128 * FIN; i += 256) {
        int r = i / FIN, f = i - r * FIN;
        xsm[i] = g_xT[((size_t)0 * BATCH + m0 + r) * FIN + f];
    }
    __syncthreads();

    // ---- A(0): h1(0) = lstm0(x0, h=0, c=0) ; acc = 0 ----
    {
        float hv[4];
#pragma unroll
        for (int j = 0; j < 4; j++) {
            int rl = rl0 + ((j & 2) ? 8 : 0);
            int cl = 2 * tq + (j & 1);
            float p[4];
#pragma unroll
            for (int s = 0; s < 4; s++)
                p[s] = b0s[s * 8 + cl] + dot10(xsm + rl * FIN, wxs + (s * 8 + cl) * FIN);
            float ig = sigmoidf_(p[0]), fg = sigmoidf_(p[1]);
            float gg = tanhf(p[2]),     og = sigmoidf_(p[3]);
            float c = fg * c1v[j] + ig * gg;
            c1v[j] = c;
            hv[j] = og * tanhf(c);
        }
        __half2* dst = (__half2*)(g_h1[0]);
        dst[((m0 + rl0) * HSZ + colb) >> 1]       = __floats2half2_rn(hv[0], hv[1]);
        dst[((m0 + rl0 + 8) * HSZ + colb) >> 1]   = __floats2half2_rn(hv[2], hv[3]);
    }
    grid_barrier();

    // ---- main loop: phase t = [ B(t) ; A(t+1) ] ----
    for (int t = 0; t < TSTEPS; t++) {
        const __half* h1cur = g_h1[t & 1];
        stageA(At, h1cur + m0 * HSZ, tid);
        if (t + 1 < TSTEPS) {
            for (int i = tid; i < 128 * FIN; i += 256) {
                int r = i / FIN, f = i - r * FIN;
                xsm[i] = g_xT[((size_t)(t + 1) * BATCH + m0 + r) * FIN + f];
            }
        }
        __syncthreads();

        float accB[4][4] = {};
        warp_mma<4>(At, Ws1, w, lane, accB, HSZ);      // h1(t) @ wih1^T
        float accA[4][4] = {};
        if (t + 1 < TSTEPS)
            warp_mma<4>(At, Ws0, w, lane, accA, HSZ);  // h1(t) @ whh0^T (for A(t+1))
        __syncthreads();

        if (t == 0) {
            for (int i = tid; i < 128 * 32; i += 256) {
                int r = i >> 5, c = (i & 31) * 8;
                *(uint4*)(At + r * PA + c) = make_uint4(0, 0, 0, 0);
            }
        } else {
            stageA(At, g_hs + (size_t)(t - 1) * BATCH * HSZ + m0 * HSZ, tid);
        }
        __syncthreads();
        warp_mma<4>(At, Ws2, w, lane, accB, HSZ);      // + h2(t-1) @ whh1^T

        // epilogue B: h2(t), c2
        {
            float hv[4];
#pragma unroll
            for (int j = 0; j < 4; j++) {
                int cl = 2 * tq + (j & 1);
                float p[4];
#pragma unroll
                for (int s = 0; s < 4; s++) p[s] = accB[s][j] + b1s[s * 8 + cl];
                float ig = sigmoidf_(p[0]), fg = sigmoidf_(p[1]);
                float gg = tanhf(p[2]),     og = sigmoidf_(p[3]);
                float c = fg * c2v[j] + ig * gg;
                c2v[j] = c;
                hv[j] = og * tanhf(c);
            }
            __half2* dst = (__half2*)(g_hs + (size_t)t * BATCH * HSZ);
            dst[((m0 + rl0) * HSZ + colb) >> 1]     = __floats2half2_rn(hv[0], hv[1]);
            dst[((m0 + rl0 + 8) * HSZ + colb) >> 1] = __floats2half2_rn(hv[2], hv[3]);
        }

        // epilogue A: h1(t+1), c1
        if (t + 1 < TSTEPS) {
            float hv[4];
#pragma unroll
            for (int j = 0; j < 4; j++) {
                int rl = rl0 + ((j & 2) ? 8 : 0);
                int cl = 2 * tq + (j & 1);
                float p[4];
#pragma unroll
                for (int s = 0; s < 4; s++)
                    p[s] = accA[s][j] + b0s[s * 8 + cl]
                         + dot10(xsm + rl * FIN, wxs + (s * 8 + cl) * FIN);
                float ig = sigmoidf_(p[0]), fg = sigmoidf_(p[1]);
                float gg = tanhf(p[2]),     og = sigmoidf_(p[3]);
                float c = fg * c1v[j] + ig * gg;
                c1v[j] = c;
                hv[j] = og * tanhf(c);
            }
            __half2* dst = (__half2*)(g_h1[(t + 1) & 1]);
            dst[((m0 + rl0) * HSZ + colb) >> 1]     = __floats2half2_rn(hv[0], hv[1]);
            dst[((m0 + rl0 + 8) * HSZ + colb) >> 1] = __floats2half2_rn(hv[2], hv[3]);
        }
        grid_barrier();
    }
}

// ---------------- advantage head: score[r] = relu(hs[r]@w1^T + b1) . w2 ----------------
__global__ void __launch_bounds__(256) k_head(const float* __restrict__ advb1,
                                              const float* __restrict__ advw2) {
    extern __shared__ char smraw[];
    __half* At  = (__half*)smraw;               // 128 x PA
    __half* Wc  = At + 128 * PA;                // 32 x PA (chunk of advw1)
    float*  b1s = (float*)(Wc + 32 * PA);       // 256
    float*  w2s = b1s + HSZ;                    // 256

    int tid = threadIdx.x;
    size_t rowbase = (size_t)blockIdx.x * 128;

    stageA(At, g_hs + rowbase * HSZ, tid);
    if (tid < HSZ) { b1s[tid] = advb1[tid]; w2s[tid] = advw2[tid]; }

    int w = tid >> 5, lane = tid & 31, g = lane >> 2, tq = lane & 3;
    float ps0 = 0.f, ps1 = 0.f;

    for (int ch = 0; ch < 8; ch++) {
        int c0 = ch * 32;
        __syncthreads();
        for (int i = tid; i < 32 * 32; i += 256) {
            int r = i >> 5, c = (i & 31) * 8;
            *(uint4*)(Wc + r * PA + c) = *(const uint4*)(g_advw1 + (c0 + r) * HSZ + c);
        }
        __syncthreads();
        float acc[4][4] = {};
        warp_mma<4>(At, Wc, w, lane, acc, HSZ);
#pragma unroll
        for (int nt = 0; nt < 4; nt++) {
#pragma unroll
            for (int j = 0; j < 4; j++) {
                int col = c0 + nt * 8 + 2 * tq + (j & 1);
                float v = acc[nt][j] + b1s[col];
                v = fmaxf(v, 0.f) * w2s[col];
                if (j & 2) ps1 += v; else ps0 += v;
            }
        }
    }
    ps0 += __shfl_xor_sync(0xffffffffu, ps0, 1);
    ps0 += __shfl_xor_sync(0xffffffffu, ps0, 2);
    ps1 += __shfl_xor_sync(0xffffffffu, ps1, 1);
    ps1 += __shfl_xor_sync(0xffffffffu, ps1, 2);
    if (tq == 0) {
        g_scores[rowbase + w * 16 + g]     = ps0;   // +b2 omitted: softmax-invariant
        g_scores[rowbase + w * 16 + g + 8] = ps1;
    }
}

// ---------------- softmax over contiguous 1024-blocks of time-major scores ----------------
__global__ void __launch_bounds__(256) k_softmax(float* __restrict__ out) {
    __shared__ float red[256];
    int row = blockIdx.x, tid = threadIdx.x;
    const float* src = g_scores + row * 1024;

    float m = -1e30f;
    for (int j = tid; j < 1024; j += 256) m = fmaxf(m, src[j]);
    red[tid] = m; __syncthreads();
    for (int s = 128; s > 0; s >>= 1) { if (tid < s) red[tid] = fmaxf(red[tid], red[tid + s]); __syncthreads(); }
    m = red[0]; __syncthreads();

    float sum = 0.f;
    float e[4];
#pragma unroll
    for (int k = 0; k < 4; k++) { e[k] = expf(src[tid + k * 256] - m); sum += e[k]; }
    red[tid] = sum; __syncthreads();
    for (int s = 128; s > 0; s >>= 1) { if (tid < s) red[tid] += red[tid + s]; __syncthreads(); }
    float inv = 1.f / red[0];
#pragma unroll
    for (int k = 0; k < 4; k++) out[row * 1024 + tid + k * 256] = e[k] * inv;
}

// ---------------- launch ----------------
extern "C" void kernel_launch(void* const* d_in, const int* in_sizes, int n_in,
                              void* d_out, int out_size) {
    (void)in_sizes; (void)n_in; (void)out_size;
    const float* x     = (const float*)d_in[0];
    const float* wih0  = (const float*)d_in[1];
    const float* whh0  = (const float*)d_in[2];
    const float* bih0  = (const float*)d_in[3];
    const float* bhh0  = (const float*)d_in[4];
    const float* wih1  = (const float*)d_in[5];
    const float* whh1  = (const float*)d_in[6];
    const float* bih1  = (const float*)d_in[7];
    const float* bhh1  = (const float*)d_in[8];
    const float* advw1 = (const float*)d_in[9];
    const float* advb1 = (const float*)d_in[10];
    const float* advw2 = (const float*)d_in[11];
    float* out = (float*)d_out;

    const int SMM = (128 + 3 * 32) * PA * 2 + (128 * FIN + 32 * FIN + 64) * 4;
    const int SMH = (128 + 32) * PA * 2 + 2 * HSZ * 4;
    cudaFuncSetAttribute(k_main, cudaFuncAttributeMaxDynamicSharedMemorySize, SMM);
    cudaFuncSetAttribute(k_head, cudaFuncAttributeMaxDynamicSharedMemorySize, SMH);

    k_prep<<<1024, 256>>>(whh0, wih1, whh1, advw1, bih0, bhh0, bih1, bhh1);
    k_xpose<<<2048, 256>>>(x);
    k_main<<<NB, 256, SMM>>>(wih0);
    k_head<<<4096, 256, SMH>>>(advb1, advw2);
    k_softmax<<<512, 256>>>(out);
}

// round 4
// speedup vs baseline: 1.4011x; 1.4011x over previous
#include <cuda_runtime.h>
#include <cuda_fp16.h>
#include <cstdint>

#define HSZ    256
#define BATCH  512
#define TSTEPS 1024
#define G4     1024
#define FIN    10
#define PA     264   // smem pitch in halves (row = 528B, 16B-aligned, conflict-free)
#define NB     128   // persistent CTAs (all co-resident, 1 CTA/SM)

// ---------------- device scratch ----------------
__device__ __half g_whh0[G4 * HSZ];
__device__ __half g_wih1[G4 * HSZ];
__device__ __half g_whh1[G4 * HSZ];
__device__ __half g_advw1[HSZ * HSZ];
__device__ float  g_bias0[G4];
__device__ float  g_bias1[G4];
__device__ float  g_xT[(size_t)TSTEPS * BATCH * FIN];
__device__ __half g_h1[2][BATCH * HSZ];
__device__ __half g_h2zero[BATCH * HSZ];
__device__ __half g_hs[(size_t)TSTEPS * BATCH * HSZ];   // h2 history == h2 state
__device__ float  g_scores[TSTEPS * BATCH];
__device__ unsigned g_bar_count;
__device__ unsigned g_bar_gen;

// ---------------- math helpers ----------------
__device__ __forceinline__ float fsigmoid(float x) {
    return __fdividef(1.f, 1.f + __expf(-x));
}
__device__ __forceinline__ float ftanh(float x) {
    float e = __expf(2.f * x);
    return 1.f - __fdividef(2.f, e + 1.f);
}
__device__ __forceinline__ float dot10(const float* a, const float* b) {
    float s = 0.f;
#pragma unroll
    for (int f = 0; f < FIN; f++) s += a[f] * b[f];
    return s;
}

// ---------------- PTX helpers ----------------
__device__ __forceinline__ void ldsm_x4(uint32_t& r0, uint32_t& r1, uint32_t& r2, uint32_t& r3,
                                        uint32_t saddr) {
    asm volatile("ldmatrix.sync.aligned.m8n8.x4.shared.b16 {%0,%1,%2,%3}, [%4];"
                 : "=r"(r0), "=r"(r1), "=r"(r2), "=r"(r3) : "r"(saddr));
}
__device__ __forceinline__ void mma16816(float* c, uint32_t a0, uint32_t a1, uint32_t a2,
                                         uint32_t a3, uint32_t b0, uint32_t b1) {
    asm volatile(
        "mma.sync.aligned.m16n8k16.row.col.f32.f16.f16.f32 "
        "{%0,%1,%2,%3},{%4,%5,%6,%7},{%8,%9},{%0,%1,%2,%3};\n"
        : "+f"(c[0]), "+f"(c[1]), "+f"(c[2]), "+f"(c[3])
        : "r"(a0), "r"(a1), "r"(a2), "r"(a3), "r"(b0), "r"(b1));
}
__device__ __forceinline__ void cpasync16(uint32_t saddr, const void* g) {
    asm volatile("cp.async.cg.shared.global [%0], [%1], 16;" :: "r"(saddr), "l"(g));
}
__device__ __forceinline__ void cp_commit() { asm volatile("cp.async.commit_group;"); }
template <int N>
__device__ __forceinline__ void cp_wait() { asm volatile("cp.async.wait_group %0;" :: "n"(N)); }

// issue 16 cp.async per thread: [128 x 256] half tile (row stride HSZ) -> smem pitch PA
__device__ __forceinline__ void cp_tile(uint32_t at_s, const __half* __restrict__ src, int tid) {
#pragma unroll
    for (int k = 0; k < 16; k++) {
        int i = tid + k * 256;
        int r = i >> 5, c = (i & 31) * 8;
        cpasync16(at_s + (r * PA + c) * 2, src + r * HSZ + c);
    }
}

// legacy scalar-LDS warp mma (used by k_head only)
template <int NT>
__device__ __forceinline__ void warp_mma(const __half* At, const __half* Ws,
                                         int w, int lane, float (&acc)[NT][4], int K) {
    int g = lane >> 2, tq = lane & 3;
    const __half* Ab = At + (w * 16 + g) * PA + 2 * tq;
    const __half* Bb = Ws + g * PA + 2 * tq;
    for (int kc = 0; kc < K; kc += 16) {
        uint32_t a0 = *(const uint32_t*)(Ab + kc);
        uint32_t a1 = *(const uint32_t*)(Ab + kc + 8 * PA);
        uint32_t a2 = *(const uint32_t*)(Ab + kc + 8);
        uint32_t a3 = *(const uint32_t*)(Ab + kc + 8 * PA + 8);
#pragma unroll
        for (int nt = 0; nt < NT; nt++) {
            const __half* Bp = Bb + nt * 8 * PA + kc;
            uint32_t b0 = *(const uint32_t*)(Bp);
            uint32_t b1 = *(const uint32_t*)(Bp + 8);
            float* c4 = acc[nt];
            mma16816(c4, a0, a1, a2, a3, b0, b1);
        }
    }
}

// sense-reversing grid barrier (cross-CTA data flows via L2: cp.async.cg / STG)
__device__ __forceinline__ void grid_barrier() {
    __syncthreads();
    if (threadIdx.x == 0) {
        __threadfence();   // publish our STGs before arrival
        unsigned gen = *(volatile unsigned*)&g_bar_gen;
        unsigned t = atomicAdd(&g_bar_count, 1u);
        if (t == NB - 1) {
            g_bar_count = 0;
            __threadfence();
            *(volatile unsigned*)&g_bar_gen = gen + 1;
        } else {
            while (*(volatile unsigned*)&g_bar_gen == gen) { __nanosleep(32); }
        }
    }
    __syncthreads();
}

// ---------------- prologue ----------------
__global__ void k_prep(const float* __restrict__ whh0, const float* __restrict__ wih1,
                       const float* __restrict__ whh1, const float* __restrict__ advw1,
                       const float* __restrict__ bih0, const float* __restrict__ bhh0,
                       const float* __restrict__ bih1, const float* __restrict__ bhh1) {
    int i = blockIdx.x * blockDim.x + threadIdx.x;
    if (i == 0) { g_bar_count = 0; g_bar_gen = 0; }
    if (i < G4 * HSZ) {
        g_whh0[i] = __float2half(whh0[i]);
        g_wih1[i] = __float2half(wih1[i]);
        g_whh1[i] = __float2half(whh1[i]);
    }
    if (i < HSZ * HSZ) g_advw1[i] = __float2half(advw1[i]);
    if (i < BATCH * HSZ) g_h2zero[i] = __float2half(0.f);
    if (i < G4) { g_bias0[i] = bih0[i] + bhh0[i]; g_bias1[i] = bih1[i] + bhh1[i]; }
}

__global__ void k_xpose(const float* __restrict__ x) {
    int idx = blockIdx.x * blockDim.x + threadIdx.x;   // idx = b*T + t
    if (idx < BATCH * TSTEPS) {
        int b = idx >> 10, t = idx & 1023;
        const float* src = x + (size_t)idx * FIN;
        float* dst = g_xT + ((size_t)t * BATCH + b) * FIN;
#pragma unroll
        for (int f = 0; f < FIN; f++) dst[f] = src[f];
    }
}

// ---------------- persistent LSTM kernel ----------------
__global__ void __launch_bounds__(256, 1) k_main(const float* __restrict__ wih0) {
    extern __shared__ char smraw[];
    __half* At1 = (__half*)smraw;               // h1 tile   128 x PA
    __half* At2 = At1 + 128 * PA;               // h2prev    128 x PA
    __half* Ws0 = At2 + 128 * PA;               // whh0 slice 32 x PA
    __half* Ws1 = Ws0 + 32 * PA;                // wih1 slice
    __half* Ws2 = Ws1 + 32 * PA;                // whh1 slice
    float*  xsm = (float*)(Ws2 + 32 * PA);      // 128 x 10
    float*  wxs = xsm + 128 * FIN;              // 32 x 10
    float*  b0s = wxs + 32 * FIN;               // 32
    float*  b1s = b0s + 32;                     // 32

    int tid = threadIdx.x;
    int m0 = (blockIdx.x >> 5) * 128;           // batch tile
    int hbase = (blockIdx.x & 31) * 8;          // h-slice

    // one-time weight staging
    for (int i = tid; i < 32 * 32; i += 256) {
        int r = i >> 5, c = (i & 31) * 8;
        int s = r >> 3, n = r & 7;
        int grow = (s * 256 + hbase + n) * HSZ + c;
        *(uint4*)(Ws0 + r * PA + c) = *(const uint4*)(g_whh0 + grow);
        *(uint4*)(Ws1 + r * PA + c) = *(const uint4*)(g_wih1 + grow);
        *(uint4*)(Ws2 + r * PA + c) = *(const uint4*)(g_whh1 + grow);
    }
    for (int i = tid; i < 32 * FIN; i += 256) {
        int r = i / FIN, f = i - r * FIN;
        int s = r >> 3, n = r & 7;
        wxs[i] = wih0[(s * 256 + hbase + n) * FIN + f];
    }
    if (tid < 32) {
        int s = tid >> 3, n = tid & 7;
        b0s[tid] = g_bias0[s * 256 + hbase + n];
        b1s[tid] = g_bias1[s * 256 + hbase + n];
    }

    int w = tid >> 5, lane = tid & 31, g = lane >> 2, tq = lane & 3;
    int quad = lane >> 3, qi = lane & 7;
    int rl0 = w * 16 + g;
    int colb = hbase + 2 * tq;

    // per-lane ldmatrix offsets (in halves)
    // A: row = w*16 + (q&1)*8 + qi ; koff = (q>>1)*8
    uint32_t a_off = ((uint32_t)(w * 16 + (quad & 1) * 8 + qi) * PA + (quad >> 1) * 8) * 2;
    uint32_t at1_s = (uint32_t)__cvta_generic_to_shared(At1);
    uint32_t at2_s = (uint32_t)__cvta_generic_to_shared(At2);
    // B: strip = 2p + (q>>1), row qi ; koff = (q&1)*8   (p handled by +16p*PA)
    uint32_t b_off = ((uint32_t)((quad >> 1) * 8 + qi) * PA + (quad & 1) * 8) * 2;
    uint32_t ws0_s = (uint32_t)__cvta_generic_to_shared(Ws0) + b_off;
    uint32_t ws1_s = (uint32_t)__cvta_generic_to_shared(Ws1) + b_off;
    uint32_t ws2_s = (uint32_t)__cvta_generic_to_shared(Ws2) + b_off;
    const uint32_t PSTRIDE = 16 * PA * 2;   // pair stride (bytes)

    float c1v[4] = {0.f, 0.f, 0.f, 0.f};
    float c2v[4] = {0.f, 0.f, 0.f, 0.f};

    // stage x(0)
    for (int i = tid; i < 128 * FIN; i += 256) {
        int r = i / FIN, f = i - r * FIN;
        xsm[i] = g_xT[((size_t)0 * BATCH + m0 + r) * FIN + f];
    }
    __syncthreads();

    // ---- A(0): h1(0) = lstm0(x0, 0, 0) ----
    {
        float hv[4];
#pragma unroll
        for (int j = 0; j < 4; j++) {
            int rl = rl0 + ((j & 2) ? 8 : 0);
            int cl = 2 * tq + (j & 1);
            float p[4];
#pragma unroll
            for (int s = 0; s < 4; s++)
                p[s] = b0s[s * 8 + cl] + dot10(xsm + rl * FIN, wxs + (s * 8 + cl) * FIN);
            float ig = fsigmoid(p[0]), fg = fsigmoid(p[1]);
            float gg = ftanh(p[2]),    og = fsigmoid(p[3]);
            float c = fg * c1v[j] + ig * gg;
            c1v[j] = c;
            hv[j] = og * ftanh(c);
        }
        __half2* dst = (__half2*)(g_h1[0]);
        dst[((m0 + rl0) * HSZ + colb) >> 1]     = __floats2half2_rn(hv[0], hv[1]);
        dst[((m0 + rl0 + 8) * HSZ + colb) >> 1] = __floats2half2_rn(hv[2], hv[3]);
    }
    grid_barrier();

    // ---- main loop: phase t = [ B(t) ; A(t+1) ] ----
    for (int t = 0; t < TSTEPS; t++) {
        const __half* h1cur  = g_h1[t & 1];
        const __half* h2prev = (t == 0) ? g_h2zero : (g_hs + (size_t)(t - 1) * BATCH * HSZ);

        cp_tile(at1_s, h1cur + m0 * HSZ, tid);  cp_commit();
        cp_tile(at2_s, h2prev + m0 * HSZ, tid); cp_commit();

        if (t + 1 < TSTEPS) {
            for (int i = tid; i < 128 * FIN; i += 256) {
                int r = i / FIN, f = i - r * FIN;
                xsm[i] = g_xT[((size_t)(t + 1) * BATCH + m0 + r) * FIN + f];
            }
        }
        cp_wait<1>();       // h1 tile landed
        __syncthreads();

        float accA[4][4] = {};   // h1 @ whh0^T (layer0, t+1)
        float accB[4][4] = {};   // h1 @ wih1^T + h2prev @ whh1^T (layer1, t)
        // pass 1: shared A fragments feed both weight matrices
#pragma unroll
        for (int kc = 0; kc < HSZ; kc += 16) {
            uint32_t a0, a1, a2, a3, b0, b1, b2, b3;
            ldsm_x4(a0, a1, a2, a3, at1_s + a_off + kc * 2);
#pragma unroll
            for (int p = 0; p < 2; p++) {
                ldsm_x4(b0, b1, b2, b3, ws0_s + p * PSTRIDE + kc * 2);
                mma16816(accA[2 * p],     a0, a1, a2, a3, b0, b1);
                mma16816(accA[2 * p + 1], a0, a1, a2, a3, b2, b3);
                ldsm_x4(b0, b1, b2, b3, ws1_s + p * PSTRIDE + kc * 2);
                mma16816(accB[2 * p],     a0, a1, a2, a3, b0, b1);
                mma16816(accB[2 * p + 1], a0, a1, a2, a3, b2, b3);
            }
        }
        cp_wait<0>();       // h2prev tile landed
        __syncthreads();
        // pass 2: h2prev @ whh1^T
#pragma unroll
        for (int kc = 0; kc < HSZ; kc += 16) {
            uint32_t a0, a1, a2, a3, b0, b1, b2, b3;
            ldsm_x4(a0, a1, a2, a3, at2_s + a_off + kc * 2);
#pragma unroll
            for (int p = 0; p < 2; p++) {
                ldsm_x4(b0, b1, b2, b3, ws2_s + p * PSTRIDE + kc * 2);
                mma16816(accB[2 * p],     a0, a1, a2, a3, b0, b1);
                mma16816(accB[2 * p + 1], a0, a1, a2, a3, b2, b3);
            }
        }

        // epilogue B: h2(t), c2
        {
            float hv[4];
#pragma unroll
            for (int j = 0; j < 4; j++) {
                int cl = 2 * tq + (j & 1);
                float p[4];
#pragma unroll
                for (int s = 0; s < 4; s++) p[s] = accB[s][j] + b1s[s * 8 + cl];
                float ig = fsigmoid(p[0]), fg = fsigmoid(p[1]);
                float gg = ftanh(p[2]),    og = fsigmoid(p[3]);
                float c = fg * c2v[j] + ig * gg;
                c2v[j] = c;
                hv[j] = og * ftanh(c);
            }
            __half2* dst = (__half2*)(g_hs + (size_t)t * BATCH * HSZ);
            dst[((m0 + rl0) * HSZ + colb) >> 1]     = __floats2half2_rn(hv[0], hv[1]);
            dst[((m0 + rl0 + 8) * HSZ + colb) >> 1] = __floats2half2_rn(hv[2], hv[3]);
        }
        // epilogue A: h1(t+1), c1
        if (t + 1 < TSTEPS) {
            float hv[4];
#pragma unroll
            for (int j = 0; j < 4; j++) {
                int rl = rl0 + ((j & 2) ? 8 : 0);
                int cl = 2 * tq + (j & 1);
                float p[4];
#pragma unroll
                for (int s = 0; s < 4; s++)
                    p[s] = accA[s][j] + b0s[s * 8 + cl]
                         + dot10(xsm + rl * FIN, wxs + (s * 8 + cl) * FIN);
                float ig = fsigmoid(p[0]), fg = fsigmoid(p[1]);
                float gg = ftanh(p[2]),    og = fsigmoid(p[3]);
                float c = fg * c1v[j] + ig * gg;
                c1v[j] = c;
                hv[j] = og * ftanh(c);
            }
            __half2* dst = (__half2*)(g_h1[(t + 1) & 1]);
            dst[((m0 + rl0) * HSZ + colb) >> 1]     = __floats2half2_rn(hv[0], hv[1]);
            dst[((m0 + rl0 + 8) * HSZ + colb) >> 1] = __floats2half2_rn(hv[2], hv[3]);
        }
        grid_barrier();
    }
}

// ---------------- advantage head ----------------
__global__ void __launch_bounds__(256) k_head(const float* __restrict__ advb1,
                                              const float* __restrict__ advw2) {
    extern __shared__ char smraw[];
    __half* At  = (__half*)smraw;               // 128 x PA
    __half* Wc  = At + 128 * PA;                // 32 x PA
    float*  b1s = (float*)(Wc + 32 * PA);       // 256
    float*  w2s = b1s + HSZ;                    // 256

    int tid = threadIdx.x;
    size_t rowbase = (size_t)blockIdx.x * 128;

    for (int i = tid; i < 128 * 32; i += 256) {
        int r = i >> 5, c = (i & 31) * 8;
        *(uint4*)(At + r * PA + c) = *(const uint4*)(g_hs + rowbase * HSZ + r * HSZ + c);
    }
    if (tid < HSZ) { b1s[tid] = advb1[tid]; w2s[tid] = advw2[tid]; }

    int w = tid >> 5, lane = tid & 31, g = lane >> 2, tq = lane & 3;
    float ps0 = 0.f, ps1 = 0.f;

    for (int ch = 0; ch < 8; ch++) {
        int c0 = ch * 32;
        __syncthreads();
        for (int i = tid; i < 32 * 32; i += 256) {
            int r = i >> 5, c = (i & 31) * 8;
            *(uint4*)(Wc + r * PA + c) = *(const uint4*)(g_advw1 + (c0 + r) * HSZ + c);
        }
        __syncthreads();
        float acc[4][4] = {};
        warp_mma<4>(At, Wc, w, lane, acc, HSZ);
#pragma unroll
        for (int nt = 0; nt < 4; nt++) {
#pragma unroll
            for (int j = 0; j < 4; j++) {
                int col = c0 + nt * 8 + 2 * tq + (j & 1);
                float v = acc[nt][j] + b1s[col];
                v = fmaxf(v, 0.f) * w2s[col];
                if (j & 2) ps1 += v; else ps0 += v;
            }
        }
    }
    ps0 += __shfl_xor_sync(0xffffffffu, ps0, 1);
    ps0 += __shfl_xor_sync(0xffffffffu, ps0, 2);
    ps1 += __shfl_xor_sync(0xffffffffu, ps1, 1);
    ps1 += __shfl_xor_sync(0xffffffffu, ps1, 2);
    if (tq == 0) {
        g_scores[rowbase + w * 16 + g]     = ps0;   // +b2 omitted: softmax-invariant
        g_scores[rowbase + w * 16 + g + 8] = ps1;
    }
}

// ---------------- softmax over contiguous 1024-blocks ----------------
__global__ void __launch_bounds__(256) k_softmax(float* __restrict__ out) {
    __shared__ float red[256];
    int row = blockIdx.x, tid = threadIdx.x;
    const float* src = g_scores + row * 1024;

    float m = -1e30f;
    for (int j = tid; j < 1024; j += 256) m = fmaxf(m, src[j]);
    red[tid] = m; __syncthreads();
    for (int s = 128; s > 0; s >>= 1) { if (tid < s) red[tid] = fmaxf(red[tid], red[tid + s]); __syncthreads(); }
    m = red[0]; __syncthreads();

    float sum = 0.f;
    float e[4];
#pragma unroll
    for (int k = 0; k < 4; k++) { e[k] = expf(src[tid + k * 256] - m); sum += e[k]; }
    red[tid] = sum; __syncthreads();
    for (int s = 128; s > 0; s >>= 1) { if (tid < s) red[tid] += red[tid + s]; __syncthreads(); }
    float inv = 1.f / red[0];
#pragma unroll
    for (int k = 0; k < 4; k++) out[row * 1024 + tid + k * 256] = e[k] * inv;
}

// ---------------- launch ----------------
extern "C" void kernel_launch(void* const* d_in, const int* in_sizes, int n_in,
                              void* d_out, int out_size) {
    (void)in_sizes; (void)n_in; (void)out_size;
    const float* x     = (const float*)d_in[0];
    const float* wih0  = (const float*)d_in[1];
    const float* whh0  = (const float*)d_in[2];
    const float* bih0  = (const float*)d_in[3];
    const float* bhh0  = (const float*)d_in[4];
    const float* wih1  = (const float*)d_in[5];
    const float* whh1  = (const float*)d_in[6];
    const float* bih1  = (const float*)d_in[7];
    const float* bhh1  = (const float*)d_in[8];
    const float* advw1 = (const float*)d_in[9];
    const float* advb1 = (const float*)d_in[10];
    const float* advw2 = (const float*)d_in[11];
    float* out = (float*)d_out;

    const int SMM = (2 * 128 + 3 * 32) * PA * 2 + (128 * FIN + 32 * FIN + 64) * 4;
    const int SMH = (128 + 32) * PA * 2 + 2 * HSZ * 4;
    cudaFuncSetAttribute(k_main, cudaFuncAttributeMaxDynamicSharedMemorySize, SMM);
    cudaFuncSetAttribute(k_head, cudaFuncAttributeMaxDynamicSharedMemorySize, SMH);

    k_prep<<<1024, 256>>>(whh0, wih1, whh1, advw1, bih0, bhh0, bih1, bhh1);
    k_xpose<<<2048, 256>>>(x);
    k_main<<<NB, 256, SMM>>>(wih0);
    k_head<<<4096, 256, SMH>>>(advb1, advw2);
    k_softmax<<<512, 256>>>(out);
}

// round 7
// speedup vs baseline: 1.9845x; 1.4164x over previous
#include <cuda_runtime.h>
#include <cuda_fp16.h>
#include <cstdint>

#define HSZ    256
#define BATCH  512
#define TSTEPS 1024
#define G4     1024
#define FIN    10
#define PA     280   // smem pitch in halves (fits K=272; stride 560B is conflict-free for ldsm)
#define NB     128   // persistent CTAs (1 CTA/SM)
#define NGRP   4     // independent batch groups
#define GRPSZ  32    // CTAs per group

// ---------------- device scratch ----------------
__device__ __half g_whh0[G4 * HSZ];
__device__ __half g_wih1[G4 * HSZ];
__device__ __half g_whh1[G4 * HSZ];
__device__ __half g_advw1[HSZ * HSZ];
__device__ float  g_bias0[G4];
__device__ float  g_bias1[G4];
__device__ __half g_xTh[(size_t)TSTEPS * BATCH * 16];   // x transposed, fp16, padded 10->16
__device__ __half g_h1[2][BATCH * HSZ];
__device__ __half g_hs[(size_t)TSTEPS * BATCH * HSZ];   // h2 history == h2 state
__device__ float  g_scores[TSTEPS * BATCH];
__device__ unsigned g_barc[NGRP * 32];                  // 128B-spaced per group
__device__ unsigned g_barg[NGRP * 32];

// ---------------- math ----------------
__device__ __forceinline__ float tanh_ap(float x) {
    float y; asm("tanh.approx.f32 %0, %1;" : "=f"(y) : "f"(x)); return y;
}
__device__ __forceinline__ float sig_ap(float x) {
    return fmaf(tanh_ap(0.5f * x), 0.5f, 0.5f);
}

// ---------------- PTX helpers ----------------
__device__ __forceinline__ void ldsm_x4(uint32_t& r0, uint32_t& r1, uint32_t& r2, uint32_t& r3,
                                        uint32_t saddr) {
    asm volatile("ldmatrix.sync.aligned.m8n8.x4.shared.b16 {%0,%1,%2,%3}, [%4];"
                 : "=r"(r0), "=r"(r1), "=r"(r2), "=r"(r3) : "r"(saddr));
}
__device__ __forceinline__ void mma16816(float* c, uint32_t a0, uint32_t a1, uint32_t a2,
                                         uint32_t a3, uint32_t b0, uint32_t b1) {
    asm volatile(
        "mma.sync.aligned.m16n8k16.row.col.f32.f16.f16.f32 "
        "{%0,%1,%2,%3},{%4,%5,%6,%7},{%8,%9},{%0,%1,%2,%3};\n"
        : "+f"(c[0]), "+f"(c[1]), "+f"(c[2]), "+f"(c[3])
        : "r"(a0), "r"(a1), "r"(a2), "r"(a3), "r"(b0), "r"(b1));
}
__device__ __forceinline__ void cpasync16(uint32_t saddr, const void* g) {
    asm volatile("cp.async.cg.shared.global [%0], [%1], 16;" :: "r"(saddr), "l"(g));
}
__device__ __forceinline__ void cp_commit() { asm volatile("cp.async.commit_group;"); }
template <int N>
__device__ __forceinline__ void cp_wait() { asm volatile("cp.async.wait_group %0;" :: "n"(N)); }

// 16 cp.async/thread: [128 x 256] half tile (row stride HSZ) -> smem pitch PA
__device__ __forceinline__ void cp_tile(uint32_t at_s, const __half* __restrict__ src, int tid) {
#pragma unroll
    for (int k = 0; k < 16; k++) {
        int i = tid + k * 256;
        int r = i >> 5, c = (i & 31) * 8;
        cpasync16(at_s + (r * PA + c) * 2, src + r * HSZ + c);
    }
}

// group-local sense-reversing barrier (32 CTAs)
__device__ __forceinline__ void grp_barrier(int grp) {
    __syncthreads();
    if (threadIdx.x == 0) {
        __threadfence();   // publish our STGs
        volatile unsigned* genp = (volatile unsigned*)&g_barg[grp * 32];
        unsigned gen = *genp;
        if (atomicAdd(&g_barc[grp * 32], 1u) == GRPSZ - 1) {
            g_barc[grp * 32] = 0;
            __threadfence();
            *genp = gen + 1;
        } else {
            while (*genp == gen) { __nanosleep(32); }
        }
    }
    __syncthreads();
}

// ---------------- prologue ----------------
__global__ void k_prep(const float* __restrict__ whh0, const float* __restrict__ wih1,
                       const float* __restrict__ whh1, const float* __restrict__ advw1,
                       const float* __restrict__ bih0, const float* __restrict__ bhh0,
                       const float* __restrict__ bih1, const float* __restrict__ bhh1) {
    int i = blockIdx.x * blockDim.x + threadIdx.x;
    if (i < NGRP) { g_barc[i * 32] = 0; g_barg[i * 32] = 0; }
    if (i < G4 * HSZ) {
        g_whh0[i] = __float2half(whh0[i]);
        g_wih1[i] = __float2half(wih1[i]);
        g_whh1[i] = __float2half(whh1[i]);
    }
    if (i < HSZ * HSZ) g_advw1[i] = __float2half(advw1[i]);
    if (i < G4) { g_bias0[i] = bih0[i] + bhh0[i]; g_bias1[i] = bih1[i] + bhh1[i]; }
}

__global__ void k_xpose(const float* __restrict__ x) {
    int idx = blockIdx.x * blockDim.x + threadIdx.x;   // idx = b*T + t
    if (idx < BATCH * TSTEPS) {
        int b = idx >> 10, t = idx & 1023;
        const float* src = x + (size_t)idx * FIN;
        __half* dst = g_xTh + ((size_t)t * BATCH + b) * 16;
#pragma unroll
        for (int f = 0; f < FIN; f++) dst[f] = __float2half(src[f]);
#pragma unroll
        for (int f = FIN; f < 16; f++) dst[f] = __float2half(0.f);
    }
}

// ---------------- persistent LSTM kernel ----------------
__global__ void __launch_bounds__(256, 1) k_main(const float* __restrict__ wih0) {
    extern __shared__ char smraw[];
    __half* At1 = (__half*)smraw;               // h1|x tile 128 x PA (cols 256..271 = x(t+1))
    __half* At2 = At1 + 128 * PA;               // h2prev    128 x PA
    __half* Ws0 = At2 + 128 * PA;               // [whh0|wih0] slice 32 x PA
    __half* Ws1 = Ws0 + 32 * PA;                // wih1 slice
    __half* Ws2 = Ws1 + 32 * PA;                // whh1 slice
    __half* xsm = Ws2 + 32 * PA;                // 128 x 16 (step-0 x)
    float*  wxs = (float*)(xsm + 128 * 16);     // 32 x 10 (step-0 wih0)
    float*  b0s = wxs + 32 * FIN;               // 32
    float*  b1s = b0s + 32;                     // 32

    int tid = threadIdx.x;
    int grp = blockIdx.x >> 5;
    int m0 = grp * 128;                          // batch tile
    int hbase = (blockIdx.x & 31) * 8;           // h-slice

    // one-time weight staging (cols 0..255)
    for (int i = tid; i < 32 * 32; i += 256) {
        int r = i >> 5, c = (i & 31) * 8;
        int s = r >> 3, n = r & 7;
        int grow = (s * 256 + hbase + n) * HSZ + c;
        *(uint4*)(Ws0 + r * PA + c) = *(const uint4*)(g_whh0 + grow);
        *(uint4*)(Ws1 + r * PA + c) = *(const uint4*)(g_wih1 + grow);
        *(uint4*)(Ws2 + r * PA + c) = *(const uint4*)(g_whh1 + grow);
    }
    // Ws0 cols 256..271 = wih0 slice (10 cols) + zero pad
    for (int i = tid; i < 32 * 16; i += 256) {
        int r = i >> 4, c = i & 15;
        int s = r >> 3, n = r & 7;
        Ws0[r * PA + 256 + c] =
            (c < FIN) ? __float2half(wih0[(s * 256 + hbase + n) * FIN + c]) : __half(__float2half(0.f));
    }
    for (int i = tid; i < 32 * FIN; i += 256) {
        int r = i / FIN, f = i - r * FIN;
        int s = r >> 3, n = r & 7;
        wxs[i] = wih0[(s * 256 + hbase + n) * FIN + f];
    }
    if (tid < 32) {
        int s = tid >> 3, n = tid & 7;
        b0s[tid] = g_bias0[s * 256 + hbase + n];
        b1s[tid] = g_bias1[s * 256 + hbase + n];
    }

    int w = tid >> 5, lane = tid & 31, g = lane >> 2, tq = lane & 3;
    int quad = lane >> 3, qi = lane & 7;
    int rl0 = w * 16 + g;
    int colb = hbase + 2 * tq;

    uint32_t a_off = ((uint32_t)(w * 16 + (quad & 1) * 8 + qi) * PA + (quad >> 1) * 8) * 2;
    uint32_t at1_s = (uint32_t)__cvta_generic_to_shared(At1);
    uint32_t at2_s = (uint32_t)__cvta_generic_to_shared(At2);
    uint32_t b_off = ((uint32_t)((quad >> 1) * 8 + qi) * PA + (quad & 1) * 8) * 2;
    uint32_t ws0_s = (uint32_t)__cvta_generic_to_shared(Ws0) + b_off;
    uint32_t ws1_s = (uint32_t)__cvta_generic_to_shared(Ws1) + b_off;
    uint32_t ws2_s = (uint32_t)__cvta_generic_to_shared(Ws2) + b_off;
    const uint32_t PSTRIDE = 16 * PA * 2;

    float c1v[4] = {0.f, 0.f, 0.f, 0.f};
    float c2v[4] = {0.f, 0.f, 0.f, 0.f};

    // ---- A(0): h1(0) = lstm0(x0, 0, 0), scalar path ----
    for (int i = tid; i < 128 * 2; i += 256) {   // 128 rows x 16 halves, 8-half chunks
        int r = i >> 1, c = (i & 1) * 8;
        *(uint4*)(xsm + r * 16 + c) = *(const uint4*)(g_xTh + ((size_t)0 * BATCH + m0 + r) * 16 + c);
    }
    __syncthreads();
    {
        float hv[4];
#pragma unroll
        for (int j = 0; j < 4; j++) {
            int rl = rl0 + ((j & 2) ? 8 : 0);
            int cl = 2 * tq + (j & 1);
            float p[4];
#pragma unroll
            for (int s = 0; s < 4; s++) {
                float acc = b0s[s * 8 + cl];
#pragma unroll
                for (int f = 0; f < FIN; f++)
                    acc += __half2float(xsm[rl * 16 + f]) * wxs[(s * 8 + cl) * FIN + f];
                p[s] = acc;
            }
            float ig = sig_ap(p[0]), fg = sig_ap(p[1]);
            float gg = tanh_ap(p[2]), og = sig_ap(p[3]);
            float c = fg * c1v[j] + ig * gg;
            c1v[j] = c;
            hv[j] = og * tanh_ap(c);
        }
        __half2* dst = (__half2*)(g_h1[0]);
        dst[((m0 + rl0) * HSZ + colb) >> 1]     = __floats2half2_rn(hv[0], hv[1]);
        dst[((m0 + rl0 + 8) * HSZ + colb) >> 1] = __floats2half2_rn(hv[2], hv[3]);
    }
    grp_barrier(grp);

    // ---- main loop: phase t = [ B(t) ; A(t+1) ] ----
    for (int t = 0; t < TSTEPS; t++) {
        const __half* h1cur  = g_h1[t & 1];
        const __half* h2prev = g_hs + (size_t)((t > 0) ? (t - 1) : 0) * BATCH * HSZ;

        // group 0: h1 tile (needed first)
        cp_tile(at1_s, h1cur + m0 * HSZ, tid);
        cp_commit();
        // group 1: x(t+1) into At1 cols 256.. + h2prev tile
        if (t + 1 < TSTEPS) {
            int r = tid >> 1, c = (tid & 1) * 8;
            cpasync16(at1_s + (r * PA + 256 + c) * 2,
                      g_xTh + ((size_t)(t + 1) * BATCH + m0 + r) * 16 + c);
        }
        if (t > 0) cp_tile(at2_s, h2prev + m0 * HSZ, tid);
        cp_commit();

        cp_wait<1>();
        __syncthreads();

        float accA[4][4] = {};   // h1 @ whh0^T (+ x @ wih0^T)  -> layer0, t+1
        float accB[4][4] = {};   // h1 @ wih1^T + h2prev @ whh1^T -> layer1, t
#pragma unroll
        for (int kc = 0; kc < HSZ; kc += 16) {
            uint32_t a0, a1, a2, a3, b0, b1, b2, b3;
            ldsm_x4(a0, a1, a2, a3, at1_s + a_off + kc * 2);
#pragma unroll
            for (int p = 0; p < 2; p++) {
                ldsm_x4(b0, b1, b2, b3, ws0_s + p * PSTRIDE + kc * 2);
                mma16816(accA[2 * p],     a0, a1, a2, a3, b0, b1);
                mma16816(accA[2 * p + 1], a0, a1, a2, a3, b2, b3);
                ldsm_x4(b0, b1, b2, b3, ws1_s + p * PSTRIDE + kc * 2);
                mma16816(accB[2 * p],     a0, a1, a2, a3, b0, b1);
                mma16816(accB[2 * p + 1], a0, a1, a2, a3, b2, b3);
            }
        }
        cp_wait<0>();
        __syncthreads();
        // x chunk (kc = 256) -> accA only
        if (t + 1 < TSTEPS) {
            uint32_t a0, a1, a2, a3, b0, b1, b2, b3;
            ldsm_x4(a0, a1, a2, a3, at1_s + a_off + 256 * 2);
#pragma unroll
            for (int p = 0; p < 2; p++) {
                ldsm_x4(b0, b1, b2, b3, ws0_s + p * PSTRIDE + 256 * 2);
                mma16816(accA[2 * p],     a0, a1, a2, a3, b0, b1);
                mma16816(accA[2 * p + 1], a0, a1, a2, a3, b2, b3);
            }
        }
        // pass 2: h2prev @ whh1^T
        if (t > 0) {
#pragma unroll
            for (int kc = 0; kc < HSZ; kc += 16) {
                uint32_t a0, a1, a2, a3, b0, b1, b2, b3;
                ldsm_x4(a0, a1, a2, a3, at2_s + a_off + kc * 2);
#pragma unroll
                for (int p = 0; p < 2; p++) {
                    ldsm_x4(b0, b1, b2, b3, ws2_s + p * PSTRIDE + kc * 2);
                    mma16816(accB[2 * p],     a0, a1, a2, a3, b0, b1);
                    mma16816(accB[2 * p + 1], a0, a1, a2, a3, b2, b3);
                }
            }
        }

        // epilogue B: h2(t), c2
        {
            float hv[4];
#pragma unroll
            for (int j = 0; j < 4; j++) {
                int cl = 2 * tq + (j & 1);
                float p[4];
#pragma unroll
                for (int s = 0; s < 4; s++) p[s] = accB[s][j] + b1s[s * 8 + cl];
                float ig = sig_ap(p[0]), fg = sig_ap(p[1]);
                float gg = tanh_ap(p[2]), og = sig_ap(p[3]);
                float c = fg * c2v[j] + ig * gg;
                c2v[j] = c;
                hv[j] = og * tanh_ap(c);
            }
            __half2* dst = (__half2*)(g_hs + (size_t)t * BATCH * HSZ);
            dst[((m0 + rl0) * HSZ + colb) >> 1]     = __floats2half2_rn(hv[0], hv[1]);
            dst[((m0 + rl0 + 8) * HSZ + colb) >> 1] = __floats2half2_rn(hv[2], hv[3]);
        }
        // epilogue A: h1(t+1), c1  (x-projection already in accA)
        if (t + 1 < TSTEPS) {
            float hv[4];
#pragma unroll
            for (int j = 0; j < 4; j++) {
                int cl = 2 * tq + (j & 1);
                float p[4];
#pragma unroll
                for (int s = 0; s < 4; s++) p[s] = accA[s][j] + b0s[s * 8 + cl];
                float ig = sig_ap(p[0]), fg = sig_ap(p[1]);
                float gg = tanh_ap(p[2]), og = sig_ap(p[3]);
                float c = fg * c1v[j] + ig * gg;
                c1v[j] = c;
                hv[j] = og * tanh_ap(c);
            }
            __half2* dst = (__half2*)(g_h1[(t + 1) & 1]);
            dst[((m0 + rl0) * HSZ + colb) >> 1]     = __floats2half2_rn(hv[0], hv[1]);
            dst[((m0 + rl0 + 8) * HSZ + colb) >> 1] = __floats2half2_rn(hv[2], hv[3]);
        }
        grp_barrier(grp);
    }
}

// ---------------- advantage head (ldmatrix path) ----------------
__global__ void __launch_bounds__(256) k_head(const float* __restrict__ advb1,
                                              const float* __restrict__ advw2) {
    extern __shared__ char smraw[];
    __half* At  = (__half*)smraw;               // 128 x PA
    __half* Wc  = At + 128 * PA;                // 32 x PA
    float*  b1s = (float*)(Wc + 32 * PA);       // 256
    float*  w2s = b1s + HSZ;                    // 256

    int tid = threadIdx.x;
    size_t rowbase = (size_t)blockIdx.x * 128;

    for (int i = tid; i < 128 * 32; i += 256) {
        int r = i >> 5, c = (i & 31) * 8;
        *(uint4*)(At + r * PA + c) = *(const uint4*)(g_hs + rowbase * HSZ + r * HSZ + c);
    }
    if (tid < HSZ) { b1s[tid] = advb1[tid]; w2s[tid] = advw2[tid]; }

    int w = tid >> 5, lane = tid & 31, g = lane >> 2, tq = lane & 3;
    int quad = lane >> 3, qi = lane & 7;
    uint32_t a_off = ((uint32_t)(w * 16 + (quad & 1) * 8 + qi) * PA + (quad >> 1) * 8) * 2;
    uint32_t at_s = (uint32_t)__cvta_generic_to_shared(At);
    uint32_t b_off = ((uint32_t)((quad >> 1) * 8 + qi) * PA + (quad & 1) * 8) * 2;
    uint32_t wc_s = (uint32_t)__cvta_generic_to_shared(Wc) + b_off;
    const uint32_t PSTRIDE = 16 * PA * 2;

    float ps0 = 0.f, ps1 = 0.f;

    for (int ch = 0; ch < 8; ch++) {
        int c0 = ch * 32;
        __syncthreads();
        for (int i = tid; i < 32 * 32; i += 256) {
            int r = i >> 5, c = (i & 31) * 8;
            *(uint4*)(Wc + r * PA + c) = *(const uint4*)(g_advw1 + (c0 + r) * HSZ + c);
        }
        __syncthreads();
        float acc[4][4] = {};
#pragma unroll
        for (int kc = 0; kc < HSZ; kc += 16) {
            uint32_t a0, a1, a2, a3, b0, b1, b2, b3;
            ldsm_x4(a0, a1, a2, a3, at_s + a_off + kc * 2);
#pragma unroll
            for (int p = 0; p < 2; p++) {
                ldsm_x4(b0, b1, b2, b3, wc_s + p * PSTRIDE + kc * 2);
                mma16816(acc[2 * p],     a0, a1, a2, a3, b0, b1);
                mma16816(acc[2 * p + 1], a0, a1, a2, a3, b2, b3);
            }
        }
#pragma unroll
        for (int nt = 0; nt < 4; nt++) {
#pragma unroll
            for (int j = 0; j < 4; j++) {
                int col = c0 + nt * 8 + 2 * tq + (j & 1);
                float v = acc[nt][j] + b1s[col];
                v = fmaxf(v, 0.f) * w2s[col];
                if (j & 2) ps1 += v; else ps0 += v;
            }
        }
    }
    ps0 += __shfl_xor_sync(0xffffffffu, ps0, 1);
    ps0 += __shfl_xor_sync(0xffffffffu, ps0, 2);
    ps1 += __shfl_xor_sync(0xffffffffu, ps1, 1);
    ps1 += __shfl_xor_sync(0xffffffffu, ps1, 2);
    int g8 = w * 16 + g;
    if (tq == 0) {
        g_scores[rowbase + g8]     = ps0;   // +b2 omitted: softmax-invariant
        g_scores[rowbase + g8 + 8] = ps1;
    }
}

// ---------------- softmax over contiguous 1024-blocks ----------------
__global__ void __launch_bounds__(256) k_softmax(float* __restrict__ out) {
    __shared__ float red[256];
    int row = blockIdx.x, tid = threadIdx.x;
    const float* src = g_scores + row * 1024;

    float m = -1e30f;
    for (int j = tid; j < 1024; j += 256) m = fmaxf(m, src[j]);
    red[tid] = m; __syncthreads();
    for (int s = 128; s > 0; s >>= 1) { if (tid < s) red[tid] = fmaxf(red[tid], red[tid + s]); __syncthreads(); }
    m = red[0]; __syncthreads();

    float sum = 0.f;
    float e[4];
#pragma unroll
    for (int k = 0; k < 4; k++) { e[k] = expf(src[tid + k * 256] - m); sum += e[k]; }
    red[tid] = sum; __syncthreads();
    for (int s = 128; s > 0; s >>= 1) { if (tid < s) red[tid] += red[tid + s]; __syncthreads(); }
    float inv = 1.f / red[0];
#pragma unroll
    for (int k = 0; k < 4; k++) out[row * 1024 + tid + k * 256] = e[k] * inv;
}

// ---------------- launch ----------------
extern "C" void kernel_launch(void* const* d_in, const int* in_sizes, int n_in,
                              void* d_out, int out_size) {
    (void)in_sizes; (void)n_in; (void)out_size;
    const float* x     = (const float*)d_in[0];
    const float* wih0  = (const float*)d_in[1];
    const float* whh0  = (const float*)d_in[2];
    const float* bih0  = (const float*)d_in[3];
    const float* bhh0  = (const float*)d_in[4];
    const float* wih1  = (const float*)d_in[5];
    const float* whh1  = (const float*)d_in[6];
    const float* bih1  = (const float*)d_in[7];
    const float* bhh1  = (const float*)d_in[8];
    const float* advw1 = (const float*)d_in[9];
    const float* advb1 = (const float*)d_in[10];
    const float* advw2 = (const float*)d_in[11];
    float* out = (float*)d_out;

    const int SMM = (2 * 128 + 3 * 32) * PA * 2 + 128 * 16 * 2 + (32 * FIN + 64) * 4;
    const int SMH = (128 + 32) * PA * 2 + 2 * HSZ * 4;
    cudaFuncSetAttribute(k_main, cudaFuncAttributeMaxDynamicSharedMemorySize, SMM);
    cudaFuncSetAttribute(k_head, cudaFuncAttributeMaxDynamicSharedMemorySize, SMH);

    k_prep<<<1024, 256>>>(whh0, wih1, whh1, advw1, bih0, bhh0, bih1, bhh1);
    k_xpose<<<2048, 256>>>(x);
    k_main<<<NB, 256, SMM>>>(wih0);
    k_head<<<4096, 256, SMH>>>(advb1, advw2);
    k_softmax<<<512, 256>>>(out);
}

// round 8
// speedup vs baseline: 1.9854x; 1.0004x over previous
#include <cuda_runtime.h>
#include <cuda_fp16.h>
#include <cstdint>

#define HSZ    256
#define BATCH  512
#define TSTEPS 1024
#define G4     1024
#define FIN    10
#define PA     280   // smem pitch in halves (fits K=272; stride 560B is conflict-free for ldsm)
#define NB     128   // persistent CTAs (1 CTA/SM)
#define NGRP   4     // independent batch groups
#define GRPSZ  32    // CTAs per group

// ---------------- device scratch ----------------
__device__ __half g_whh0[G4 * HSZ];
__device__ __half g_wih1[G4 * HSZ];
__device__ __half g_whh1[G4 * HSZ];
__device__ __half g_advw1[HSZ * HSZ];
__device__ float  g_bias0[G4];
__device__ float  g_bias1[G4];
__device__ __half g_xTh[(size_t)TSTEPS * BATCH * 16];   // x transposed, fp16, padded 10->16
__device__ __half g_h1[2][BATCH * HSZ];
__device__ __half g_hs[(size_t)TSTEPS * BATCH * HSZ];   // h2 history == h2 state
__device__ float  g_scores[TSTEPS * BATCH];
__device__ unsigned g_barc[NGRP * 32];                  // 128B-spaced per group
__device__ unsigned g_barg[NGRP * 32];

// ---------------- math ----------------
__device__ __forceinline__ float tanh_ap(float x) {
    float y; asm("tanh.approx.f32 %0, %1;" : "=f"(y) : "f"(x)); return y;
}
__device__ __forceinline__ float sig_ap(float x) {
    return fmaf(tanh_ap(0.5f * x), 0.5f, 0.5f);
}

// ---------------- PTX helpers ----------------
__device__ __forceinline__ void ldsm_x4(uint32_t& r0, uint32_t& r1, uint32_t& r2, uint32_t& r3,
                                        uint32_t saddr) {
    asm volatile("ldmatrix.sync.aligned.m8n8.x4.shared.b16 {%0,%1,%2,%3}, [%4];"
                 : "=r"(r0), "=r"(r1), "=r"(r2), "=r"(r3) : "r"(saddr));
}
__device__ __forceinline__ void mma16816(float* c, uint32_t a0, uint32_t a1, uint32_t a2,
                                         uint32_t a3, uint32_t b0, uint32_t b1) {
    asm volatile(
        "mma.sync.aligned.m16n8k16.row.col.f32.f16.f16.f32 "
        "{%0,%1,%2,%3},{%4,%5,%6,%7},{%8,%9},{%0,%1,%2,%3};\n"
        : "+f"(c[0]), "+f"(c[1]), "+f"(c[2]), "+f"(c[3])
        : "r"(a0), "r"(a1), "r"(a2), "r"(a3), "r"(b0), "r"(b1));
}
__device__ __forceinline__ void cpasync16(uint32_t saddr, const void* g) {
    asm volatile("cp.async.cg.shared.global [%0], [%1], 16;" :: "r"(saddr), "l"(g));
}
__device__ __forceinline__ void cp_commit() { asm volatile("cp.async.commit_group;"); }
template <int N>
__device__ __forceinline__ void cp_wait() { asm volatile("cp.async.wait_group %0;" :: "n"(N)); }

// 16 cp.async/thread: [128 x 256] half tile (row stride HSZ) -> smem pitch PA
__device__ __forceinline__ void cp_tile(uint32_t at_s, const __half* __restrict__ src, int tid) {
#pragma unroll
    for (int k = 0; k < 16; k++) {
        int i = tid + k * 256;
        int r = i >> 5, c = (i & 31) * 8;
        cpasync16(at_s + (r * PA + c) * 2, src + r * HSZ + c);
    }
}

// group-local sense-reversing barrier (32 CTAs)
__device__ __forceinline__ void grp_barrier(int grp) {
    __syncthreads();
    if (threadIdx.x == 0) {
        __threadfence();   // publish our STGs
        volatile unsigned* genp = (volatile unsigned*)&g_barg[grp * 32];
        unsigned gen = *genp;
        if (atomicAdd(&g_barc[grp * 32], 1u) == GRPSZ - 1) {
            g_barc[grp * 32] = 0;
            __threadfence();
            *genp = gen + 1;
        } else {
            while (*genp == gen) { __nanosleep(32); }
        }
    }
    __syncthreads();
}

// ---------------- prologue ----------------
__global__ void k_prep(const float* __restrict__ whh0, const float* __restrict__ wih1,
                       const float* __restrict__ whh1, const float* __restrict__ advw1,
                       const float* __restrict__ bih0, const float* __restrict__ bhh0,
                       const float* __restrict__ bih1, const float* __restrict__ bhh1) {
    int i = blockIdx.x * blockDim.x + threadIdx.x;
    if (i < NGRP) { g_barc[i * 32] = 0; g_barg[i * 32] = 0; }
    if (i < G4 * HSZ) {
        g_whh0[i] = __float2half(whh0[i]);
        g_wih1[i] = __float2half(wih1[i]);
        g_whh1[i] = __float2half(whh1[i]);
    }
    if (i < HSZ * HSZ) g_advw1[i] = __float2half(advw1[i]);
    if (i < G4) { g_bias0[i] = bih0[i] + bhh0[i]; g_bias1[i] = bih1[i] + bhh1[i]; }
}

__global__ void k_xpose(const float* __restrict__ x) {
    int idx = blockIdx.x * blockDim.x + threadIdx.x;   // idx = b*T + t
    if (idx < BATCH * TSTEPS) {
        int b = idx >> 10, t = idx & 1023;
        const float* src = x + (size_t)idx * FIN;
        __half* dst = g_xTh + ((size_t)t * BATCH + b) * 16;
#pragma unroll
        for (int f = 0; f < FIN; f++) dst[f] = __float2half(src[f]);
#pragma unroll
        for (int f = FIN; f < 16; f++) dst[f] = __float2half(0.f);
    }
}

// ---------------- persistent LSTM kernel ----------------
__global__ void __launch_bounds__(256, 1) k_main(const float* __restrict__ wih0) {
    extern __shared__ char smraw[];
    __half* At1 = (__half*)smraw;               // h1|x tile 128 x PA (cols 256..271 = x(t+1))
    __half* At2 = At1 + 128 * PA;               // h2prev    128 x PA
    __half* Ws0 = At2 + 128 * PA;               // [whh0|wih0] slice 32 x PA
    __half* Ws1 = Ws0 + 32 * PA;                // wih1 slice
    __half* Ws2 = Ws1 + 32 * PA;                // whh1 slice
    __half* xsm = Ws2 + 32 * PA;                // 128 x 16 (step-0 x)
    float*  wxs = (float*)(xsm + 128 * 16);     // 32 x 10 (step-0 wih0)
    float*  b0s = wxs + 32 * FIN;               // 32
    float*  b1s = b0s + 32;                     // 32

    int tid = threadIdx.x;
    int grp = blockIdx.x >> 5;
    int m0 = grp * 128;                          // batch tile
    int hbase = (blockIdx.x & 31) * 8;           // h-slice

    // one-time weight staging (cols 0..255)
    for (int i = tid; i < 32 * 32; i += 256) {
        int r = i >> 5, c = (i & 31) * 8;
        int s = r >> 3, n = r & 7;
        int grow = (s * 256 + hbase + n) * HSZ + c;
        *(uint4*)(Ws0 + r * PA + c) = *(const uint4*)(g_whh0 + grow);
        *(uint4*)(Ws1 + r * PA + c) = *(const uint4*)(g_wih1 + grow);
        *(uint4*)(Ws2 + r * PA + c) = *(const uint4*)(g_whh1 + grow);
    }
    // Ws0 cols 256..271 = wih0 slice (10 cols) + zero pad
    for (int i = tid; i < 32 * 16; i += 256) {
        int r = i >> 4, c = i & 15;
        int s = r >> 3, n = r & 7;
        Ws0[r * PA + 256 + c] =
            (c < FIN) ? __float2half(wih0[(s * 256 + hbase + n) * FIN + c]) : __half(__float2half(0.f));
    }
    for (int i = tid; i < 32 * FIN; i += 256) {
        int r = i / FIN, f = i - r * FIN;
        int s = r >> 3, n = r & 7;
        wxs[i] = wih0[(s * 256 + hbase + n) * FIN + f];
    }
    if (tid < 32) {
        int s = tid >> 3, n = tid & 7;
        b0s[tid] = g_bias0[s * 256 + hbase + n];
        b1s[tid] = g_bias1[s * 256 + hbase + n];
    }

    int w = tid >> 5, lane = tid & 31, g = lane >> 2, tq = lane & 3;
    int quad = lane >> 3, qi = lane & 7;
    int rl0 = w * 16 + g;
    int colb = hbase + 2 * tq;

    uint32_t a_off = ((uint32_t)(w * 16 + (quad & 1) * 8 + qi) * PA + (quad >> 1) * 8) * 2;
    uint32_t at1_s = (uint32_t)__cvta_generic_to_shared(At1);
    uint32_t at2_s = (uint32_t)__cvta_generic_to_shared(At2);
    uint32_t b_off = ((uint32_t)((quad >> 1) * 8 + qi) * PA + (quad & 1) * 8) * 2;
    uint32_t ws0_s = (uint32_t)__cvta_generic_to_shared(Ws0) + b_off;
    uint32_t ws1_s = (uint32_t)__cvta_generic_to_shared(Ws1) + b_off;
    uint32_t ws2_s = (uint32_t)__cvta_generic_to_shared(Ws2) + b_off;
    const uint32_t PSTRIDE = 16 * PA * 2;

    float c1v[4] = {0.f, 0.f, 0.f, 0.f};
    float c2v[4] = {0.f, 0.f, 0.f, 0.f};

    // ---- A(0): h1(0) = lstm0(x0, 0, 0), scalar path ----
    for (int i = tid; i < 128 * 2; i += 256) {   // 128 rows x 16 halves, 8-half chunks
        int r = i >> 1, c = (i & 1) * 8;
        *(uint4*)(xsm + r * 16 + c) = *(const uint4*)(g_xTh + ((size_t)0 * BATCH + m0 + r) * 16 + c);
    }
    __syncthreads();
    {
        float hv[4];
#pragma unroll
        for (int j = 0; j < 4; j++) {
            int rl = rl0 + ((j & 2) ? 8 : 0);
            int cl = 2 * tq + (j & 1);
            float p[4];
#pragma unroll
            for (int s = 0; s < 4; s++) {
                float acc = b0s[s * 8 + cl];
#pragma unroll
                for (int f = 0; f < FIN; f++)
                    acc += __half2float(xsm[rl * 16 + f]) * wxs[(s * 8 + cl) * FIN + f];
                p[s] = acc;
            }
            float ig = sig_ap(p[0]), fg = sig_ap(p[1]);
            float gg = tanh_ap(p[2]), og = sig_ap(p[3]);
            float c = fg * c1v[j] + ig * gg;
            c1v[j] = c;
            hv[j] = og * tanh_ap(c);
        }
        __half2* dst = (__half2*)(g_h1[0]);
        dst[((m0 + rl0) * HSZ + colb) >> 1]     = __floats2half2_rn(hv[0], hv[1]);
        dst[((m0 + rl0 + 8) * HSZ + colb) >> 1] = __floats2half2_rn(hv[2], hv[3]);
    }
    grp_barrier(grp);

    // ---- main loop: phase t = [ B(t) ; A(t+1) ] ----
    for (int t = 0; t < TSTEPS; t++) {
        const __half* h1cur  = g_h1[t & 1];
        const __half* h2prev = g_hs + (size_t)((t > 0) ? (t - 1) : 0) * BATCH * HSZ;

        // group 0: h1 tile (needed first)
        cp_tile(at1_s, h1cur + m0 * HSZ, tid);
        cp_commit();
        // group 1: x(t+1) into At1 cols 256.. + h2prev tile
        if (t + 1 < TSTEPS) {
            int r = tid >> 1, c = (tid & 1) * 8;
            cpasync16(at1_s + (r * PA + 256 + c) * 2,
                      g_xTh + ((size_t)(t + 1) * BATCH + m0 + r) * 16 + c);
        }
        if (t > 0) cp_tile(at2_s, h2prev + m0 * HSZ, tid);
        cp_commit();

        cp_wait<1>();
        __syncthreads();

        float accA[4][4] = {};   // h1 @ whh0^T (+ x @ wih0^T)  -> layer0, t+1
        float accB[4][4] = {};   // h1 @ wih1^T + h2prev @ whh1^T -> layer1, t
#pragma unroll
        for (int kc = 0; kc < HSZ; kc += 16) {
            uint32_t a0, a1, a2, a3, b0, b1, b2, b3;
            ldsm_x4(a0, a1, a2, a3, at1_s + a_off + kc * 2);
#pragma unroll
            for (int p = 0; p < 2; p++) {
                ldsm_x4(b0, b1, b2, b3, ws0_s + p * PSTRIDE + kc * 2);
                mma16816(accA[2 * p],     a0, a1, a2, a3, b0, b1);
                mma16816(accA[2 * p + 1], a0, a1, a2, a3, b2, b3);
                ldsm_x4(b0, b1, b2, b3, ws1_s + p * PSTRIDE + kc * 2);
                mma16816(accB[2 * p],     a0, a1, a2, a3, b0, b1);
                mma16816(accB[2 * p + 1], a0, a1, a2, a3, b2, b3);
            }
        }
        cp_wait<0>();
        __syncthreads();
        // x chunk (kc = 256) -> accA only
        if (t + 1 < TSTEPS) {
            uint32_t a0, a1, a2, a3, b0, b1, b2, b3;
            ldsm_x4(a0, a1, a2, a3, at1_s + a_off + 256 * 2);
#pragma unroll
            for (int p = 0; p < 2; p++) {
                ldsm_x4(b0, b1, b2, b3, ws0_s + p * PSTRIDE + 256 * 2);
                mma16816(accA[2 * p],     a0, a1, a2, a3, b0, b1);
                mma16816(accA[2 * p + 1], a0, a1, a2, a3, b2, b3);
            }
        }
        // pass 2: h2prev @ whh1^T
        if (t > 0) {
#pragma unroll
            for (int kc = 0; kc < HSZ; kc += 16) {
                uint32_t a0, a1, a2, a3, b0, b1, b2, b3;
                ldsm_x4(a0, a1, a2, a3, at2_s + a_off + kc * 2);
#pragma unroll
                for (int p = 0; p < 2; p++) {
                    ldsm_x4(b0, b1, b2, b3, ws2_s + p * PSTRIDE + kc * 2);
                    mma16816(accB[2 * p],     a0, a1, a2, a3, b0, b1);
                    mma16816(accB[2 * p + 1], a0, a1, a2, a3, b2, b3);
                }
            }
        }

        // epilogue B: h2(t), c2
        {
            float hv[4];
#pragma unroll
            for (int j = 0; j < 4; j++) {
                int cl = 2 * tq + (j & 1);
                float p[4];
#pragma unroll
                for (int s = 0; s < 4; s++) p[s] = accB[s][j] + b1s[s * 8 + cl];
                float ig = sig_ap(p[0]), fg = sig_ap(p[1]);
                float gg = tanh_ap(p[2]), og = sig_ap(p[3]);
                float c = fg * c2v[j] + ig * gg;
                c2v[j] = c;
                hv[j] = og * tanh_ap(c);
            }
            __half2* dst = (__half2*)(g_hs + (size_t)t * BATCH * HSZ);
            dst[((m0 + rl0) * HSZ + colb) >> 1]     = __floats2half2_rn(hv[0], hv[1]);
            dst[((m0 + rl0 + 8) * HSZ + colb) >> 1] = __floats2half2_rn(hv[2], hv[3]);
        }
        // epilogue A: h1(t+1), c1  (x-projection already in accA)
        if (t + 1 < TSTEPS) {
            float hv[4];
#pragma unroll
            for (int j = 0; j < 4; j++) {
                int cl = 2 * tq + (j & 1);
                float p[4];
#pragma unroll
                for (int s = 0; s < 4; s++) p[s] = accA[s][j] + b0s[s * 8 + cl];
                float ig = sig_ap(p[0]), fg = sig_ap(p[1]);
                float gg = tanh_ap(p[2]), og = sig_ap(p[3]);
                float c = fg * c1v[j] + ig * gg;
                c1v[j] = c;
                hv[j] = og * tanh_ap(c);
            }
            __half2* dst = (__half2*)(g_h1[(t + 1) & 1]);
            dst[((m0 + rl0) * HSZ + colb) >> 1]     = __floats2half2_rn(hv[0], hv[1]);
            dst[((m0 + rl0 + 8) * HSZ + colb) >> 1] = __floats2half2_rn(hv[2], hv[3]);
        }
        grp_barrier(grp);
    }
}

// ---------------- advantage head (ldmatrix path) ----------------
__global__ void __launch_bounds__(256) k_head(const float* __restrict__ advb1,
                                              const float* __restrict__ advw2) {
    extern __shared__ char smraw[];
    __half* At  = (__half*)smraw;               // 128 x PA
    __half* Wc  = At + 128 * PA;                // 32 x PA
    float*  b1s = (float*)(Wc + 32 * PA);       // 256
    float*  w2s = b1s + HSZ;                    // 256

    int tid = threadIdx.x;
    size_t rowbase = (size_t)blockIdx.x * 128;

    for (int i = tid; i < 128 * 32; i += 256) {
        int r = i >> 5, c = (i & 31) * 8;
        *(uint4*)(At + r * PA + c) = *(const uint4*)(g_hs + rowbase * HSZ + r * HSZ + c);
    }
    if (tid < HSZ) { b1s[tid] = advb1[tid]; w2s[tid] = advw2[tid]; }

    int w = tid >> 5, lane = tid & 31, g = lane >> 2, tq = lane & 3;
    int quad = lane >> 3, qi = lane & 7;
    uint32_t a_off = ((uint32_t)(w * 16 + (quad & 1) * 8 + qi) * PA + (quad >> 1) * 8) * 2;
    uint32_t at_s = (uint32_t)__cvta_generic_to_shared(At);
    uint32_t b_off = ((uint32_t)((quad >> 1) * 8 + qi) * PA + (quad & 1) * 8) * 2;
    uint32_t wc_s = (uint32_t)__cvta_generic_to_shared(Wc) + b_off;
    const uint32_t PSTRIDE = 16 * PA * 2;

    float ps0 = 0.f, ps1 = 0.f;

    for (int ch = 0; ch < 8; ch++) {
        int c0 = ch * 32;
        __syncthreads();
        for (int i = tid; i < 32 * 32; i += 256) {
            int r = i >> 5, c = (i & 31) * 8;
            *(uint4*)(Wc + r * PA + c) = *(const uint4*)(g_advw1 + (c0 + r) * HSZ + c);
        }
        __syncthreads();
        float acc[4][4] = {};
#pragma unroll
        for (int kc = 0; kc < HSZ; kc += 16) {
            uint32_t a0, a1, a2, a3, b0, b1, b2, b3;
            ldsm_x4(a0, a1, a2, a3, at_s + a_off + kc * 2);
#pragma unroll
            for (int p = 0; p < 2; p++) {
                ldsm_x4(b0, b1, b2, b3, wc_s + p * PSTRIDE + kc * 2);
                mma16816(acc[2 * p],     a0, a1, a2, a3, b0, b1);
                mma16816(acc[2 * p + 1], a0, a1, a2, a3, b2, b3);
            }
        }
#pragma unroll
        for (int nt = 0; nt < 4; nt++) {
#pragma unroll
            for (int j = 0; j < 4; j++) {
                int col = c0 + nt * 8 + 2 * tq + (j & 1);
                float v = acc[nt][j] + b1s[col];
                v = fmaxf(v, 0.f) * w2s[col];
                if (j & 2) ps1 += v; else ps0 += v;
            }
        }
    }
    ps0 += __shfl_xor_sync(0xffffffffu, ps0, 1);
    ps0 += __shfl_xor_sync(0xffffffffu, ps0, 2);
    ps1 += __shfl_xor_sync(0xffffffffu, ps1, 1);
    ps1 += __shfl_xor_sync(0xffffffffu, ps1, 2);
    int g8 = w * 16 + g;
    if (tq == 0) {
        g_scores[rowbase + g8]     = ps0;   // +b2 omitted: softmax-invariant
        g_scores[rowbase + g8 + 8] = ps1;
    }
}

// ---------------- softmax over contiguous 1024-blocks ----------------
__global__ void __launch_bounds__(256) k_softmax(float* __restrict__ out) {
    __shared__ float red[256];
    int row = blockIdx.x, tid = threadIdx.x;
    const float* src = g_scores + row * 1024;

    float m = -1e30f;
    for (int j = tid; j < 1024; j += 256) m = fmaxf(m, src[j]);
    red[tid] = m; __syncthreads();
    for (int s = 128; s > 0; s >>= 1) { if (tid < s) red[tid] = fmaxf(red[tid], red[tid + s]); __syncthreads(); }
    m = red[0]; __syncthreads();

    float sum = 0.f;
    float e[4];
#pragma unroll
    for (int k = 0; k < 4; k++) { e[k] = expf(src[tid + k * 256] - m); sum += e[k]; }
    red[tid] = sum; __syncthreads();
    for (int s = 128; s > 0; s >>= 1) { if (tid < s) red[tid] += red[tid + s]; __syncthreads(); }
    float inv = 1.f / red[0];
#pragma unroll
    for (int k = 0; k < 4; k++) out[row * 1024 + tid + k * 256] = e[k] * inv;
}

// ---------------- launch ----------------
extern "C" void kernel_launch(void* const* d_in, const int* in_sizes, int n_in,
                              void* d_out, int out_size) {
    (void)in_sizes; (void)n_in; (void)out_size;
    const float* x     = (const float*)d_in[0];
    const float* wih0  = (const float*)d_in[1];
    const float* whh0  = (const float*)d_in[2];
    const float* bih0  = (const float*)d_in[3];
    const float* bhh0  = (const float*)d_in[4];
    const float* wih1  = (const float*)d_in[5];
    const float* whh1  = (const float*)d_in[6];
    const float* bih1  = (const float*)d_in[7];
    const float* bhh1  = (const float*)d_in[8];
    const float* advw1 = (const float*)d_in[9];
    const float* advb1 = (const float*)d_in[10];
    const float* advw2 = (const float*)d_in[11];
    float* out = (float*)d_out;

    const int SMM = (2 * 128 + 3 * 32) * PA * 2 + 128 * 16 * 2 + (32 * FIN + 64) * 4;
    const int SMH = (128 + 32) * PA * 2 + 2 * HSZ * 4;
    cudaFuncSetAttribute(k_main, cudaFuncAttributeMaxDynamicSharedMemorySize, SMM);
    cudaFuncSetAttribute(k_head, cudaFuncAttributeMaxDynamicSharedMemorySize, SMH);

    k_prep<<<1024, 256>>>(whh0, wih1, whh1, advw1, bih0, bhh0, bih1, bhh1);
    k_xpose<<<2048, 256>>>(x);
    k_main<<<NB, 256, SMM>>>(wih0);
    k_head<<<4096, 256, SMH>>>(advb1, advw2);
    k_softmax<<<512, 256>>>(out);
}